// round 2
// baseline (speedup 1.0000x reference)
#include <cuda_runtime.h>

#define N_PTS  262144
#define NLVL   16
#define TBL_T  (1u << 19)
#define TMASK  (TBL_T - 1u)
#define P1     2654435761u
#define P2     805459861u

// floor(16 * 128^(l/15)) for l = 0..15 (float32, matching numpy reference)
__constant__ float c_res[NLVL] = {
    16.f, 22.f, 30.f, 42.f, 58.f, 80.f, 111.f, 153.f,
    212.f, 294.f, 406.f, 561.f, 776.f, 1072.f, 1482.f, 2048.f
};

__global__ __launch_bounds__(128)
void ngp_fused(const float* __restrict__ x,
               const float* __restrict__ dvec,
               const float2* __restrict__ table,
               const float* __restrict__ g_w0,    // (64,32)
               const float* __restrict__ g_wout,  // (16,64)
               const float* __restrict__ g_rw0,   // (64,32)
               const float* __restrict__ g_rw1,   // (64,64)
               const float* __restrict__ g_rwout, // (3,64)
               float* __restrict__ out)           // [N sigmas][N*3 rgbs]
{
    __shared__ float s_w0   [64 * 32];  // [j][t]      row-major
    __shared__ float s_woutT[64 * 16];  // [j][k]      transposed
    __shared__ float s_rw0  [64 * 32];  // [j][t]      row-major
    __shared__ float s_rw1T [64 * 64];  // [j][k]      transposed
    __shared__ float s_rwout[3 * 64];   // [c][k]      row-major

    const int tid = threadIdx.x;
    for (int t = tid; t < 64 * 32; t += 128) s_w0[t]  = g_w0[t];
    for (int t = tid; t < 64 * 16; t += 128) {
        int j = t >> 4, k = t & 15;
        s_woutT[t] = g_wout[k * 64 + j];
    }
    for (int t = tid; t < 64 * 32; t += 128) s_rw0[t] = g_rw0[t];
    for (int t = tid; t < 64 * 64; t += 128) {
        int j = t >> 6, k = t & 63;
        s_rw1T[t] = g_rw1[k * 64 + j];
    }
    for (int t = tid; t < 3 * 64;  t += 128) s_rwout[t] = g_rwout[t];
    __syncthreads();

    const int i = blockIdx.x * 128 + tid;   // grid is exact: 2048 * 128 = N_PTS

    // ---------------- hash encoding ----------------
    const float px = x[3 * i + 0] + 0.5f;
    const float py = x[3 * i + 1] + 0.5f;
    const float pz = x[3 * i + 2] + 0.5f;

    float emb[32];

    #pragma unroll 1
    for (int l = 0; l < NLVL; ++l) {
        const float r  = c_res[l];
        const float fx = px * r, fy = py * r, fz = pz * r;
        const float ix = floorf(fx), iy = floorf(fy), iz = floorf(fz);
        const float tx = fx - ix, ty = fy - iy, tz = fz - iz;

        const unsigned xi = (unsigned)ix, yi = (unsigned)iy, zi = (unsigned)iz;
        const unsigned a0 = xi,            a1 = xi + 1u;
        const unsigned b0 = yi * P1,       b1 = (yi + 1u) * P1;
        const unsigned c0 = zi * P2,       c1 = (zi + 1u) * P2;

        const float2* tab = table + (size_t)l * TBL_T;

        const float2 f000 = __ldg(tab + ((a0 ^ b0 ^ c0) & TMASK));
        const float2 f001 = __ldg(tab + ((a0 ^ b0 ^ c1) & TMASK));
        const float2 f010 = __ldg(tab + ((a0 ^ b1 ^ c0) & TMASK));
        const float2 f011 = __ldg(tab + ((a0 ^ b1 ^ c1) & TMASK));
        const float2 f100 = __ldg(tab + ((a1 ^ b0 ^ c0) & TMASK));
        const float2 f101 = __ldg(tab + ((a1 ^ b0 ^ c1) & TMASK));
        const float2 f110 = __ldg(tab + ((a1 ^ b1 ^ c0) & TMASK));
        const float2 f111 = __ldg(tab + ((a1 ^ b1 ^ c1) & TMASK));

        const float ux = 1.f - tx, uy = 1.f - ty, uz = 1.f - tz;
        const float w000 = ux * uy * uz, w001 = ux * uy * tz;
        const float w010 = ux * ty * uz, w011 = ux * ty * tz;
        const float w100 = tx * uy * uz, w101 = tx * uy * tz;
        const float w110 = tx * ty * uz, w111 = tx * ty * tz;

        float e0 = w000 * f000.x + w001 * f001.x;
        float e1 = w000 * f000.y + w001 * f001.y;
        e0 += w010 * f010.x + w011 * f011.x;
        e1 += w010 * f010.y + w011 * f011.y;
        e0 += w100 * f100.x + w101 * f101.x;
        e1 += w100 * f100.y + w101 * f101.y;
        e0 += w110 * f110.x + w111 * f111.x;
        e1 += w110 * f110.y + w111 * f111.y;

        emb[2 * l + 0] = e0;
        emb[2 * l + 1] = e1;
    }

    // ---------------- xyz MLP: 32 -> 64 (relu) -> 16 ----------------
    float h[16];
    #pragma unroll
    for (int k = 0; k < 16; ++k) h[k] = 0.f;

    #pragma unroll 1
    for (int j = 0; j < 64; ++j) {
        const float4* wr = (const float4*)(s_w0 + j * 32);
        float p0 = 0.f, q0 = 0.f, p1 = 0.f, q1 = 0.f;
        #pragma unroll
        for (int q = 0; q < 8; ++q) {
            const float4 w = wr[q];
            p0 += w.x * emb[4 * q + 0];
            q0 += w.y * emb[4 * q + 1];
            p1 += w.z * emb[4 * q + 2];
            q1 += w.w * emb[4 * q + 3];
        }
        float acc = (p0 + q0) + (p1 + q1);
        acc = fmaxf(acc, 0.f);

        const float4* wo = (const float4*)(s_woutT + j * 16);
        #pragma unroll
        for (int q = 0; q < 4; ++q) {
            const float4 w = wo[q];
            h[4 * q + 0] += w.x * acc;
            h[4 * q + 1] += w.y * acc;
            h[4 * q + 2] += w.z * acc;
            h[4 * q + 3] += w.w * acc;
        }
    }

    out[i] = expf(h[0]);   // sigma

    // ---------------- SH encoding (deg 4) ----------------
    const float dx0 = dvec[3 * i + 0];
    const float dy0 = dvec[3 * i + 1];
    const float dz0 = dvec[3 * i + 2];
    const float inv = rsqrtf(dx0 * dx0 + dy0 * dy0 + dz0 * dz0);
    const float X = dx0 * inv, Y = dy0 * inv, Z = dz0 * inv;
    const float xx = X * X, yy = Y * Y, zz = Z * Z;

    float f[32];
    f[0]  = 0.28209479177387814f;
    f[1]  = -0.4886025119029199f * Y;
    f[2]  =  0.4886025119029199f * Z;
    f[3]  = -0.4886025119029199f * X;
    f[4]  =  1.0925484305920792f * (X * Y);
    f[5]  = -1.0925484305920792f * (Y * Z);
    f[6]  =  0.31539156525252005f * (3.0f * zz - 1.0f);
    f[7]  = -1.0925484305920792f * (X * Z);
    f[8]  =  0.5462742152960396f * (xx - yy);
    f[9]  = -0.5900435899266435f * Y * (3.0f * xx - yy);
    f[10] =  2.890611442640554f  * (X * Y) * Z;
    f[11] = -0.4570457994644658f * Y * (4.0f * zz - xx - yy);
    f[12] =  0.3731763325901154f * Z * (2.0f * zz - 3.0f * xx - 3.0f * yy);
    f[13] = -0.4570457994644658f * X * (4.0f * zz - xx - yy);
    f[14] =  1.445305721320277f  * Z * (xx - yy);
    f[15] = -0.5900435899266435f * X * (xx - 3.0f * yy);
    #pragma unroll
    for (int k = 0; k < 16; ++k) f[16 + k] = h[k];

    // ---------------- rgb MLP: 32 -> 64 (relu) -> 64 (relu) -> 3 (sigmoid) ----
    float a1[64];
    #pragma unroll
    for (int k = 0; k < 64; ++k) a1[k] = 0.f;

    #pragma unroll 1
    for (int j = 0; j < 64; ++j) {
        const float4* wr = (const float4*)(s_rw0 + j * 32);
        float p0 = 0.f, q0 = 0.f, p1 = 0.f, q1 = 0.f;
        #pragma unroll
        for (int q = 0; q < 8; ++q) {
            const float4 w = wr[q];
            p0 += w.x * f[4 * q + 0];
            q0 += w.y * f[4 * q + 1];
            p1 += w.z * f[4 * q + 2];
            q1 += w.w * f[4 * q + 3];
        }
        float acc = (p0 + q0) + (p1 + q1);
        acc = fmaxf(acc, 0.f);

        const float4* w1 = (const float4*)(s_rw1T + j * 64);
        #pragma unroll
        for (int q = 0; q < 16; ++q) {
            const float4 w = w1[q];
            a1[4 * q + 0] += w.x * acc;
            a1[4 * q + 1] += w.y * acc;
            a1[4 * q + 2] += w.z * acc;
            a1[4 * q + 3] += w.w * acc;
        }
    }

    #pragma unroll
    for (int k = 0; k < 64; ++k) a1[k] = fmaxf(a1[k], 0.f);

    #pragma unroll
    for (int c = 0; c < 3; ++c) {
        const float4* wo = (const float4*)(s_rwout + c * 64);
        float p0 = 0.f, q0 = 0.f, p1 = 0.f, q1 = 0.f;
        #pragma unroll
        for (int q = 0; q < 16; ++q) {
            const float4 w = wo[q];
            p0 += w.x * a1[4 * q + 0];
            q0 += w.y * a1[4 * q + 1];
            p1 += w.z * a1[4 * q + 2];
            q1 += w.w * a1[4 * q + 3];
        }
        const float acc = (p0 + q0) + (p1 + q1);
        out[N_PTS + 3 * i + c] = 1.0f / (1.0f + expf(-acc));
    }
}

extern "C" void kernel_launch(void* const* d_in, const int* in_sizes, int n_in,
                              void* d_out, int out_size)
{
    const float*  x     = (const float*)d_in[0];
    const float*  d     = (const float*)d_in[1];
    const float2* table = (const float2*)d_in[2];
    const float*  w0    = (const float*)d_in[3];
    const float*  wout  = (const float*)d_in[4];
    const float*  rw0   = (const float*)d_in[5];
    const float*  rw1   = (const float*)d_in[6];
    const float*  rwout = (const float*)d_in[7];
    float* out = (float*)d_out;

    ngp_fused<<<N_PTS / 128, 128>>>(x, d, table, w0, wout, rw0, rw1, rwout, out);
}

// round 3
// speedup vs baseline: 1.1832x; 1.1832x over previous
#include <cuda_runtime.h>

#define N_PTS  262144
#define NLVL   16
#define TBL_T  (1u << 19)
#define TMASK  (TBL_T - 1u)
#define P1     2654435761u
#define P2     805459861u

// floor(16 * 128^(l/15)) for l = 0..15
__constant__ float c_res[NLVL] = {
    16.f, 22.f, 30.f, 42.f, 58.f, 80.f, 111.f, 153.f,
    212.f, 294.f, 406.f, 561.f, 776.f, 1072.f, 1482.f, 2048.f
};

// All MLP weights in constant memory (uniform across warp -> LDCU / uniform port,
// keeps the L1tex pipe free for the hash-table gathers).
__constant__ float c_w0   [64 * 32];  // (64,32) row-major
__constant__ float c_wout [16 * 64];  // (16,64) row-major
__constant__ float c_rw0  [64 * 32];  // (64,32) row-major
__constant__ float c_rw1  [64 * 64];  // (64,64) row-major
__constant__ float c_rwout[3  * 64];  // (3,64)  row-major

__global__ __launch_bounds__(128, 4)
void ngp_fused(const float* __restrict__ x,
               const float* __restrict__ dvec,
               const float2* __restrict__ table,
               float* __restrict__ out)           // [N sigmas][N*3 rgbs]
{
    const int i = blockIdx.x * 128 + threadIdx.x;  // grid exact: 2048*128 = N_PTS

    // ---------------- hash encoding ----------------
    const float px = x[3 * i + 0] + 0.5f;
    const float py = x[3 * i + 1] + 0.5f;
    const float pz = x[3 * i + 2] + 0.5f;

    float emb[32];

    #pragma unroll 1
    for (int l = 0; l < NLVL; ++l) {
        const float r  = c_res[l];
        const float fx = px * r, fy = py * r, fz = pz * r;
        const float ix = floorf(fx), iy = floorf(fy), iz = floorf(fz);
        const float tx = fx - ix, ty = fy - iy, tz = fz - iz;

        const unsigned xi = (unsigned)ix, yi = (unsigned)iy, zi = (unsigned)iz;
        const unsigned a0 = xi,            a1 = xi + 1u;
        const unsigned b0 = yi * P1,       b1 = (yi + 1u) * P1;
        const unsigned c0 = zi * P2,       c1 = (zi + 1u) * P2;

        const float2* tab = table + (size_t)l * TBL_T;

        const float2 f000 = __ldg(tab + ((a0 ^ b0 ^ c0) & TMASK));
        const float2 f001 = __ldg(tab + ((a0 ^ b0 ^ c1) & TMASK));
        const float2 f010 = __ldg(tab + ((a0 ^ b1 ^ c0) & TMASK));
        const float2 f011 = __ldg(tab + ((a0 ^ b1 ^ c1) & TMASK));
        const float2 f100 = __ldg(tab + ((a1 ^ b0 ^ c0) & TMASK));
        const float2 f101 = __ldg(tab + ((a1 ^ b0 ^ c1) & TMASK));
        const float2 f110 = __ldg(tab + ((a1 ^ b1 ^ c0) & TMASK));
        const float2 f111 = __ldg(tab + ((a1 ^ b1 ^ c1) & TMASK));

        const float ux = 1.f - tx, uy = 1.f - ty, uz = 1.f - tz;
        const float w000 = ux * uy * uz, w001 = ux * uy * tz;
        const float w010 = ux * ty * uz, w011 = ux * ty * tz;
        const float w100 = tx * uy * uz, w101 = tx * uy * tz;
        const float w110 = tx * ty * uz, w111 = tx * ty * tz;

        float e0 = w000 * f000.x + w001 * f001.x;
        float e1 = w000 * f000.y + w001 * f001.y;
        e0 += w010 * f010.x + w011 * f011.x;
        e1 += w010 * f010.y + w011 * f011.y;
        e0 += w100 * f100.x + w101 * f101.x;
        e1 += w100 * f100.y + w101 * f101.y;
        e0 += w110 * f110.x + w111 * f111.x;
        e1 += w110 * f110.y + w111 * f111.y;

        emb[2 * l + 0] = e0;
        emb[2 * l + 1] = e1;
    }

    // ---------------- xyz MLP: 32 -> 64 (relu) ----------------
    float act[64];
    #pragma unroll 4
    for (int j = 0; j < 64; ++j) {
        const float4* wr = (const float4*)(c_w0 + j * 32);
        float p0 = 0.f, q0 = 0.f, p1 = 0.f, q1 = 0.f;
        #pragma unroll
        for (int q = 0; q < 8; ++q) {
            const float4 w = wr[q];
            p0 += w.x * emb[4 * q + 0];
            q0 += w.y * emb[4 * q + 1];
            p1 += w.z * emb[4 * q + 2];
            q1 += w.w * emb[4 * q + 3];
        }
        act[j] = fmaxf((p0 + q0) + (p1 + q1), 0.f);
    }

    // ---------------- xyz out: 64 -> 16 (row-contiguous wout) ----------------
    float h[16];
    #pragma unroll
    for (int k = 0; k < 16; ++k) {
        const float4* wr = (const float4*)(c_wout + k * 64);
        float p0 = 0.f, q0 = 0.f, p1 = 0.f, q1 = 0.f;
        #pragma unroll
        for (int q = 0; q < 16; ++q) {
            const float4 w = wr[q];
            p0 += w.x * act[4 * q + 0];
            q0 += w.y * act[4 * q + 1];
            p1 += w.z * act[4 * q + 2];
            q1 += w.w * act[4 * q + 3];
        }
        h[k] = (p0 + q0) + (p1 + q1);
    }

    out[i] = expf(h[0]);   // sigma

    // ---------------- SH encoding (deg 4) ----------------
    const float dx0 = dvec[3 * i + 0];
    const float dy0 = dvec[3 * i + 1];
    const float dz0 = dvec[3 * i + 2];
    const float inv = rsqrtf(dx0 * dx0 + dy0 * dy0 + dz0 * dz0);
    const float X = dx0 * inv, Y = dy0 * inv, Z = dz0 * inv;
    const float xx = X * X, yy = Y * Y, zz = Z * Z;

    float f[32];
    f[0]  = 0.28209479177387814f;
    f[1]  = -0.4886025119029199f * Y;
    f[2]  =  0.4886025119029199f * Z;
    f[3]  = -0.4886025119029199f * X;
    f[4]  =  1.0925484305920792f * (X * Y);
    f[5]  = -1.0925484305920792f * (Y * Z);
    f[6]  =  0.31539156525252005f * (3.0f * zz - 1.0f);
    f[7]  = -1.0925484305920792f * (X * Z);
    f[8]  =  0.5462742152960396f * (xx - yy);
    f[9]  = -0.5900435899266435f * Y * (3.0f * xx - yy);
    f[10] =  2.890611442640554f  * (X * Y) * Z;
    f[11] = -0.4570457994644658f * Y * (4.0f * zz - xx - yy);
    f[12] =  0.3731763325901154f * Z * (2.0f * zz - 3.0f * xx - 3.0f * yy);
    f[13] = -0.4570457994644658f * X * (4.0f * zz - xx - yy);
    f[14] =  1.445305721320277f  * Z * (xx - yy);
    f[15] = -0.5900435899266435f * X * (xx - 3.0f * yy);
    #pragma unroll
    for (int k = 0; k < 16; ++k) f[16 + k] = h[k];

    // ---------------- rgb layer1: 32 -> 64 (relu) ----------------
    float act1[64];
    #pragma unroll 4
    for (int j = 0; j < 64; ++j) {
        const float4* wr = (const float4*)(c_rw0 + j * 32);
        float p0 = 0.f, q0 = 0.f, p1 = 0.f, q1 = 0.f;
        #pragma unroll
        for (int q = 0; q < 8; ++q) {
            const float4 w = wr[q];
            p0 += w.x * f[4 * q + 0];
            q0 += w.y * f[4 * q + 1];
            p1 += w.z * f[4 * q + 2];
            q1 += w.w * f[4 * q + 3];
        }
        act1[j] = fmaxf((p0 + q0) + (p1 + q1), 0.f);
    }

    // ---------------- rgb layer2 (64->64 relu) fused with output (64->3) ----
    float r0 = 0.f, r1 = 0.f, r2 = 0.f;
    #pragma unroll 4
    for (int k = 0; k < 64; ++k) {
        const float4* wr = (const float4*)(c_rw1 + k * 64);
        float p0 = 0.f, q0 = 0.f, p1 = 0.f, q1 = 0.f;
        #pragma unroll
        for (int q = 0; q < 16; ++q) {
            const float4 w = wr[q];
            p0 += w.x * act1[4 * q + 0];
            q0 += w.y * act1[4 * q + 1];
            p1 += w.z * act1[4 * q + 2];
            q1 += w.w * act1[4 * q + 3];
        }
        const float t = fmaxf((p0 + q0) + (p1 + q1), 0.f);
        r0 += c_rwout[0 * 64 + k] * t;
        r1 += c_rwout[1 * 64 + k] * t;
        r2 += c_rwout[2 * 64 + k] * t;
    }

    out[N_PTS + 3 * i + 0] = 1.0f / (1.0f + expf(-r0));
    out[N_PTS + 3 * i + 1] = 1.0f / (1.0f + expf(-r1));
    out[N_PTS + 3 * i + 2] = 1.0f / (1.0f + expf(-r2));
}

extern "C" void kernel_launch(void* const* d_in, const int* in_sizes, int n_in,
                              void* d_out, int out_size)
{
    const float*  x     = (const float*)d_in[0];
    const float*  d     = (const float*)d_in[1];
    const float2* table = (const float2*)d_in[2];

    // Stage weights into constant memory (D2D memcpy nodes; graph-capturable).
    cudaMemcpyToSymbolAsync(c_w0,    d_in[3], 64 * 32 * sizeof(float), 0,
                            cudaMemcpyDeviceToDevice, 0);
    cudaMemcpyToSymbolAsync(c_wout,  d_in[4], 16 * 64 * sizeof(float), 0,
                            cudaMemcpyDeviceToDevice, 0);
    cudaMemcpyToSymbolAsync(c_rw0,   d_in[5], 64 * 32 * sizeof(float), 0,
                            cudaMemcpyDeviceToDevice, 0);
    cudaMemcpyToSymbolAsync(c_rw1,   d_in[6], 64 * 64 * sizeof(float), 0,
                            cudaMemcpyDeviceToDevice, 0);
    cudaMemcpyToSymbolAsync(c_rwout, d_in[7], 3  * 64 * sizeof(float), 0,
                            cudaMemcpyDeviceToDevice, 0);

    float* out = (float*)d_out;
    ngp_fused<<<N_PTS / 128, 128>>>(x, d, table, out);
}

// round 5
// speedup vs baseline: 1.3696x; 1.1575x over previous
#include <cuda_runtime.h>

#define N_PTS  262144
#define NLVL   16
#define TBL_T  (1u << 19)
#define TMASK  (TBL_T - 1u)
#define P1     2654435761u
#define P2     805459861u

typedef unsigned long long ull;

// floor(16 * 128^(l/15)) for l = 0..15
__constant__ float c_res[NLVL] = {
    16.f, 22.f, 30.f, 42.f, 58.f, 80.f, 111.f, 153.f,
    212.f, 294.f, 406.f, 561.f, 776.f, 1072.f, 1482.f, 2048.f
};

// All MLP weights in constant memory (LDC.64 pair loads; keeps L1tex free for gathers).
__constant__ float c_w0   [64 * 32];  // (64,32) row-major
__constant__ float c_wout [16 * 64];  // (16,64) row-major
__constant__ float c_rw0  [64 * 32];  // (64,32) row-major
__constant__ float c_rw1  [64 * 64];  // (64,64) row-major
__constant__ float c_rwout[3  * 64];  // (3,64)  row-major

// ---- packed f32x2 helpers (sm_100a FFMA2 — only reachable via PTX) ----
__device__ __forceinline__ ull pack2(float lo, float hi) {
    ull r; asm("mov.b64 %0, {%1, %2};" : "=l"(r) : "f"(lo), "f"(hi)); return r;
}
__device__ __forceinline__ void unpack2(ull v, float& lo, float& hi) {
    asm("mov.b64 {%0, %1}, %2;" : "=f"(lo), "=f"(hi) : "l"(v));
}
__device__ __forceinline__ ull fma2(ull a, ull b, ull c) {
    ull d; asm("fma.rn.f32x2 %0, %1, %2, %3;" : "=l"(d) : "l"(a), "l"(b), "l"(c));
    return d;
}
__device__ __forceinline__ float hsum2(ull a, ull b) {   // sum of all 4 lanes
    float x0, x1, y0, y1;
    unpack2(a, x0, x1); unpack2(b, y0, y1);
    return (x0 + x1) + (y0 + y1);
}

__global__ __launch_bounds__(128, 4)
void ngp_fused(const float* __restrict__ x,
               const float* __restrict__ dvec,
               const float2* __restrict__ table,
               float* __restrict__ out)           // [N sigmas][N*3 rgbs]
{
    const int i = blockIdx.x * 128 + threadIdx.x;  // grid exact: 2048*128 = N_PTS

    // ---------------- hash encoding ----------------
    const float px = x[3 * i + 0] + 0.5f;
    const float py = x[3 * i + 1] + 0.5f;
    const float pz = x[3 * i + 2] + 0.5f;

    ull emb2[16];   // 32 features as 16 packed pairs (2l, 2l+1)

    #pragma unroll 1
    for (int l = 0; l < NLVL; ++l) {
        const float r  = c_res[l];
        const float fx = px * r, fy = py * r, fz = pz * r;
        const float ix = floorf(fx), iy = floorf(fy), iz = floorf(fz);
        const float tx = fx - ix, ty = fy - iy, tz = fz - iz;

        const unsigned xi = (unsigned)ix, yi = (unsigned)iy, zi = (unsigned)iz;
        const unsigned a0 = xi,            a1 = xi + 1u;
        const unsigned b0 = yi * P1,       b1 = (yi + 1u) * P1;
        const unsigned c0 = zi * P2,       c1 = (zi + 1u) * P2;

        const float2* tab = table + (size_t)l * TBL_T;

        const float2 f000 = __ldg(tab + ((a0 ^ b0 ^ c0) & TMASK));
        const float2 f001 = __ldg(tab + ((a0 ^ b0 ^ c1) & TMASK));
        const float2 f010 = __ldg(tab + ((a0 ^ b1 ^ c0) & TMASK));
        const float2 f011 = __ldg(tab + ((a0 ^ b1 ^ c1) & TMASK));
        const float2 f100 = __ldg(tab + ((a1 ^ b0 ^ c0) & TMASK));
        const float2 f101 = __ldg(tab + ((a1 ^ b0 ^ c1) & TMASK));
        const float2 f110 = __ldg(tab + ((a1 ^ b1 ^ c0) & TMASK));
        const float2 f111 = __ldg(tab + ((a1 ^ b1 ^ c1) & TMASK));

        const float ux = 1.f - tx, uy = 1.f - ty, uz = 1.f - tz;
        const float w000 = ux * uy * uz, w001 = ux * uy * tz;
        const float w010 = ux * ty * uz, w011 = ux * ty * tz;
        const float w100 = tx * uy * uz, w101 = tx * uy * tz;
        const float w110 = tx * ty * uz, w111 = tx * ty * tz;

        float e0 = w000 * f000.x + w001 * f001.x;
        float e1 = w000 * f000.y + w001 * f001.y;
        e0 += w010 * f010.x + w011 * f011.x;
        e1 += w010 * f010.y + w011 * f011.y;
        e0 += w100 * f100.x + w101 * f101.x;
        e1 += w100 * f100.y + w101 * f101.y;
        e0 += w110 * f110.x + w111 * f111.x;
        e1 += w110 * f110.y + w111 * f111.y;

        emb2[l] = pack2(e0, e1);
    }

    // ---------------- xyz MLP: 32 -> 64 (relu), packed ----------------
    ull act2[32];   // 64 activations as 32 pairs
    #pragma unroll 4
    for (int j = 0; j < 64; j += 2) {
        float s0, s1;
        {
            const ull* w = (const ull*)(c_w0 + j * 32);
            ull a0 = 0ull, a1 = 0ull;
            #pragma unroll
            for (int q = 0; q < 8; ++q) {
                a0 = fma2(w[2 * q + 0], emb2[2 * q + 0], a0);
                a1 = fma2(w[2 * q + 1], emb2[2 * q + 1], a1);
            }
            s0 = fmaxf(hsum2(a0, a1), 0.f);
        }
        {
            const ull* w = (const ull*)(c_w0 + (j + 1) * 32);
            ull a0 = 0ull, a1 = 0ull;
            #pragma unroll
            for (int q = 0; q < 8; ++q) {
                a0 = fma2(w[2 * q + 0], emb2[2 * q + 0], a0);
                a1 = fma2(w[2 * q + 1], emb2[2 * q + 1], a1);
            }
            s1 = fmaxf(hsum2(a0, a1), 0.f);
        }
        act2[j >> 1] = pack2(s0, s1);
    }

    // ---------------- xyz out: 64 -> 16, packed ----------------
    float h[16];
    #pragma unroll
    for (int k = 0; k < 16; ++k) {
        const ull* w = (const ull*)(c_wout + k * 64);
        ull a0 = 0ull, a1 = 0ull;
        #pragma unroll
        for (int q = 0; q < 16; ++q) {
            a0 = fma2(w[2 * q + 0], act2[2 * q + 0], a0);
            a1 = fma2(w[2 * q + 1], act2[2 * q + 1], a1);
        }
        h[k] = hsum2(a0, a1);
    }

    out[i] = expf(h[0]);   // sigma

    // ---------------- SH encoding (deg 4) ----------------
    const float dx0 = dvec[3 * i + 0];
    const float dy0 = dvec[3 * i + 1];
    const float dz0 = dvec[3 * i + 2];
    const float inv = rsqrtf(dx0 * dx0 + dy0 * dy0 + dz0 * dz0);
    const float X = dx0 * inv, Y = dy0 * inv, Z = dz0 * inv;
    const float xx = X * X, yy = Y * Y, zz = Z * Z;

    float f[16];
    f[0]  = 0.28209479177387814f;
    f[1]  = -0.4886025119029199f * Y;
    f[2]  =  0.4886025119029199f * Z;
    f[3]  = -0.4886025119029199f * X;
    f[4]  =  1.0925484305920792f * (X * Y);
    f[5]  = -1.0925484305920792f * (Y * Z);
    f[6]  =  0.31539156525252005f * (3.0f * zz - 1.0f);
    f[7]  = -1.0925484305920792f * (X * Z);
    f[8]  =  0.5462742152960396f * (xx - yy);
    f[9]  = -0.5900435899266435f * Y * (3.0f * xx - yy);
    f[10] =  2.890611442640554f  * (X * Y) * Z;
    f[11] = -0.4570457994644658f * Y * (4.0f * zz - xx - yy);
    f[12] =  0.3731763325901154f * Z * (2.0f * zz - 3.0f * xx - 3.0f * yy);
    f[13] = -0.4570457994644658f * X * (4.0f * zz - xx - yy);
    f[14] =  1.445305721320277f  * Z * (xx - yy);
    f[15] = -0.5900435899266435f * X * (xx - 3.0f * yy);

    ull f2[16];     // [sh(16) | h(16)] as 16 pairs
    #pragma unroll
    for (int k = 0; k < 8; ++k) f2[k]     = pack2(f[2 * k], f[2 * k + 1]);
    #pragma unroll
    for (int k = 0; k < 8; ++k) f2[8 + k] = pack2(h[2 * k], h[2 * k + 1]);

    // ---------------- rgb layer1: 32 -> 64 (relu), packed ----------------
    ull act1[32];
    #pragma unroll 4
    for (int j = 0; j < 64; j += 2) {
        float s0, s1;
        {
            const ull* w = (const ull*)(c_rw0 + j * 32);
            ull a0 = 0ull, a1 = 0ull;
            #pragma unroll
            for (int q = 0; q < 8; ++q) {
                a0 = fma2(w[2 * q + 0], f2[2 * q + 0], a0);
                a1 = fma2(w[2 * q + 1], f2[2 * q + 1], a1);
            }
            s0 = fmaxf(hsum2(a0, a1), 0.f);
        }
        {
            const ull* w = (const ull*)(c_rw0 + (j + 1) * 32);
            ull a0 = 0ull, a1 = 0ull;
            #pragma unroll
            for (int q = 0; q < 8; ++q) {
                a0 = fma2(w[2 * q + 0], f2[2 * q + 0], a0);
                a1 = fma2(w[2 * q + 1], f2[2 * q + 1], a1);
            }
            s1 = fmaxf(hsum2(a0, a1), 0.f);
        }
        act1[j >> 1] = pack2(s0, s1);
    }

    // ------- rgb layer2 (64->64 relu) fused with output (64->3), packed ------
    const ull* wo0 = (const ull*)(c_rwout + 0 * 64);
    const ull* wo1 = (const ull*)(c_rwout + 1 * 64);
    const ull* wo2 = (const ull*)(c_rwout + 2 * 64);
    ull racc0 = 0ull, racc1 = 0ull, racc2 = 0ull;

    #pragma unroll 2
    for (int k = 0; k < 64; k += 2) {
        float t0, t1;
        {
            const ull* w = (const ull*)(c_rw1 + k * 64);
            ull a0 = 0ull, a1 = 0ull;
            #pragma unroll
            for (int q = 0; q < 16; ++q) {
                a0 = fma2(w[2 * q + 0], act1[2 * q + 0], a0);
                a1 = fma2(w[2 * q + 1], act1[2 * q + 1], a1);
            }
            t0 = fmaxf(hsum2(a0, a1), 0.f);
        }
        {
            const ull* w = (const ull*)(c_rw1 + (k + 1) * 64);
            ull a0 = 0ull, a1 = 0ull;
            #pragma unroll
            for (int q = 0; q < 16; ++q) {
                a0 = fma2(w[2 * q + 0], act1[2 * q + 0], a0);
                a1 = fma2(w[2 * q + 1], act1[2 * q + 1], a1);
            }
            t1 = fmaxf(hsum2(a0, a1), 0.f);
        }
        const ull tt = pack2(t0, t1);
        racc0 = fma2(wo0[k >> 1], tt, racc0);
        racc1 = fma2(wo1[k >> 1], tt, racc1);
        racc2 = fma2(wo2[k >> 1], tt, racc2);
    }

    float u0, v0, u1, v1, u2, v2;
    unpack2(racc0, u0, v0);
    unpack2(racc1, u1, v1);
    unpack2(racc2, u2, v2);
    out[N_PTS + 3 * i + 0] = 1.0f / (1.0f + expf(-(u0 + v0)));
    out[N_PTS + 3 * i + 1] = 1.0f / (1.0f + expf(-(u1 + v1)));
    out[N_PTS + 3 * i + 2] = 1.0f / (1.0f + expf(-(u2 + v2)));
}

extern "C" void kernel_launch(void* const* d_in, const int* in_sizes, int n_in,
                              void* d_out, int out_size)
{
    const float*  x     = (const float*)d_in[0];
    const float*  d     = (const float*)d_in[1];
    const float2* table = (const float2*)d_in[2];

    // Stage weights into constant memory (D2D memcpy nodes; graph-capturable).
    cudaMemcpyToSymbolAsync(c_w0,    d_in[3], 64 * 32 * sizeof(float), 0,
                            cudaMemcpyDeviceToDevice, 0);
    cudaMemcpyToSymbolAsync(c_wout,  d_in[4], 16 * 64 * sizeof(float), 0,
                            cudaMemcpyDeviceToDevice, 0);
    cudaMemcpyToSymbolAsync(c_rw0,   d_in[5], 64 * 32 * sizeof(float), 0,
                            cudaMemcpyDeviceToDevice, 0);
    cudaMemcpyToSymbolAsync(c_rw1,   d_in[6], 64 * 64 * sizeof(float), 0,
                            cudaMemcpyDeviceToDevice, 0);
    cudaMemcpyToSymbolAsync(c_rwout, d_in[7], 3  * 64 * sizeof(float), 0,
                            cudaMemcpyDeviceToDevice, 0);

    float* out = (float*)d_out;
    ngp_fused<<<N_PTS / 128, 128>>>(x, d, table, out);
}